// round 5
// baseline (speedup 1.0000x reference)
#include <cuda_runtime.h>

// GRU: B=256, T=2048, I=10, H=64. PyTorch gate order (r, z, n).
// grid=128 CTAs x 512 threads = 2 streams (1 batch each) x 256 threads.
// Lane quad (4u..4u+3) owns hidden unit u; each lane computes ALL gates
// (r,z,n) over a 16-wide k-slice (f32x2 over k-pairs); quads merge with a
// 2-level shfl.bfly (no barrier). One named barrier per timestep
// (double-buffered h). gi precomputed per 32-step chunk (one gate row per
// lane e=0,1,2) into three f32 shared planes.

#define B_    256
#define T_    2048
#define I_    10
#define H_    64
#define CHUNK 32
#define TPB   512
#define STPB  256

typedef unsigned long long ull;

__device__ __forceinline__ ull ffma2(ull a, ull b, ull c) {
    ull d;
    asm("fma.rn.f32x2 %0, %1, %2, %3;" : "=l"(d) : "l"(a), "l"(b), "l"(c));
    return d;
}
__device__ __forceinline__ ull fadd2(ull a, ull b) {
    ull d;
    asm("add.rn.f32x2 %0, %1, %2;" : "=l"(d) : "l"(a), "l"(b));
    return d;
}
__device__ __forceinline__ ull pack2(float x, float y) {
    ull d;
    asm("mov.b64 %0, {%1, %2};" : "=l"(d) : "f"(x), "f"(y));
    return d;
}
__device__ __forceinline__ void unpack2(ull a, float& x, float& y) {
    asm("mov.b64 {%0, %1}, %2;" : "=f"(x), "=f"(y) : "l"(a));
}
__device__ __forceinline__ float tanha(float x) {
    float y;
    asm("tanh.approx.f32 %0, %1;" : "=f"(y) : "f"(x));
    return y;
}
__device__ __forceinline__ void bar_sync(int id) {
    asm volatile("bar.sync %0, %1;" :: "r"(id), "r"(STPB) : "memory");
}

__global__ void __launch_bounds__(TPB, 1)
gru_kernel(const float* __restrict__ noise,
           const float* __restrict__ w_ih,
           const float* __restrict__ w_hh,
           const float* __restrict__ b_ih,
           const float* __restrict__ b_hh,
           float* __restrict__ out)
{
    extern __shared__ __align__(16) float dyn[];
    // per-stream layout (floats): gr[CHUNK*H] gz[CHUNK*H] gn[CHUNK*H] x[CHUNK*I] h[2*H]
    const int SSZ = 3 * CHUNK * H_ + CHUNK * I_ + 2 * H_;

    const int tid = threadIdx.x;
    const int s   = tid / STPB;     // stream (batch within CTA)
    const int ts  = tid % STPB;
    const int u   = ts >> 2;        // hidden unit 0..63
    const int e   = ts & 3;         // k-slice: [16e, 16e+16)
    const int b   = blockIdx.x * 2 + s;
    const int k0  = 16 * e;
    const int BAR = 1 + s;

    float* gr = dyn + s * SSZ;
    float* gz = gr + CHUNK * H_;
    float* gn = gz + CHUNK * H_;
    float* xs = gn + CHUNK * H_;
    float* hb = xs + CHUNK * I_;

    // W_hh k-slices, packed by adjacent k-pairs.
    ull whr[8], whz[8], whn[8];
#pragma unroll
    for (int m = 0; m < 8; m++) {
        whr[m] = pack2(w_hh[(0 * H_ + u) * H_ + k0 + 2 * m], w_hh[(0 * H_ + u) * H_ + k0 + 2 * m + 1]);
        whz[m] = pack2(w_hh[(1 * H_ + u) * H_ + k0 + 2 * m], w_hh[(1 * H_ + u) * H_ + k0 + 2 * m + 1]);
        whn[m] = pack2(w_hh[(2 * H_ + u) * H_ + k0 + 2 * m], w_hh[(2 * H_ + u) * H_ + k0 + 2 * m + 1]);
    }
    // gi rows: lane e<3 owns gate e's W_ih row for unit u.
    ull wi[5];
    float bsum = 0.0f;
    if (e < 3) {
        const int row = e * H_ + u;
#pragma unroll
        for (int p = 0; p < 5; p++)
            wi[p] = pack2(w_ih[row * I_ + 2 * p], w_ih[row * I_ + 2 * p + 1]);
        bsum = b_ih[row] + (e < 2 ? b_hh[row] : 0.0f);   // fold b_hh into r,z only
    }
    const float bhn = b_hh[2 * H_ + u];                  // n hidden bias (inside r*(.))

    if (ts < 2 * H_) hb[ts] = 0.0f;
    float hreg = 0.0f;
    int p = 0;

    const float* xb = noise + (size_t)b * T_ * I_;
    float* op = out + (size_t)b * T_ * H_ + u;
    __syncthreads();

    for (int t0 = 0; t0 < T_; t0 += CHUNK) {
        // Stage x chunk (contiguous).
        for (int idx = ts; idx < CHUNK * I_; idx += STPB)
            xs[idx] = xb[t0 * I_ + idx];
        bar_sync(BAR);

        // Precompute gi for the chunk: lane e computes gate-e rows.
        if (e < 3) {
            const ull* xp = (const ull*)xs;
            float* gout = (e == 0) ? gr : (e == 1) ? gz : gn;
#pragma unroll 4
            for (int tl = 0; tl < CHUNK; tl++) {
                const ull* xt = xp + tl * (I_ / 2);
                ull a = 0ull;
#pragma unroll
                for (int q = 0; q < 5; q++)
                    a = ffma2(xt[q], wi[q], a);
                float x, y;
                unpack2(a, x, y);
                gout[tl * H_ + u] = x + y + bsum;
            }
        }
        bar_sync(BAR);

        // Recurrent loop: one barrier per step.
        for (int tl = 0; tl < CHUNK; tl++) {
            const ulonglong2* hq = (const ulonglong2*)(hb + p * H_ + k0);
            ull r0 = 0ull, r1 = 0ull, z0 = 0ull, z1 = 0ull, n0 = 0ull, n1 = 0ull;
#pragma unroll
            for (int m = 0; m < 4; m++) {
                ulonglong2 h2 = hq[m];
                r0 = ffma2(h2.x, whr[2 * m], r0);
                z0 = ffma2(h2.x, whz[2 * m], z0);
                n0 = ffma2(h2.x, whn[2 * m], n0);
                r1 = ffma2(h2.y, whr[2 * m + 1], r1);
                z1 = ffma2(h2.y, whz[2 * m + 1], z1);
                n1 = ffma2(h2.y, whn[2 * m + 1], n1);
            }
            float hvr, hvz, hvn;
            {
                float x, y;
                ull t = fadd2(r0, r1); unpack2(t, x, y); hvr = x + y;
                t = fadd2(z0, z1);     unpack2(t, x, y); hvz = x + y;
                t = fadd2(n0, n1);     unpack2(t, x, y); hvn = x + y;
            }
            // Butterfly merge across the 4-lane quad (same warp).
            hvr += __shfl_xor_sync(0xffffffffu, hvr, 1);
            hvz += __shfl_xor_sync(0xffffffffu, hvz, 1);
            hvn += __shfl_xor_sync(0xffffffffu, hvn, 1);
            hvr += __shfl_xor_sync(0xffffffffu, hvr, 2);
            hvz += __shfl_xor_sync(0xffffffffu, hvz, 2);
            hvn += __shfl_xor_sync(0xffffffffu, hvn, 2);

            const float grv = gr[tl * H_ + u];
            const float gzv = gz[tl * H_ + u];
            const float gnv = gn[tl * H_ + u];

            const float r = fmaf(0.5f, tanha(0.5f * (grv + hvr)), 0.5f);
            const float z = fmaf(0.5f, tanha(0.5f * (gzv + hvz)), 0.5f);
            const float n = tanha(fmaf(r, hvn + bhn, gnv));
            hreg = fmaf(z, hreg - n, n);            // (1-z)*n + z*h

            if (e == 0) {
                hb[(p ^ 1) * H_ + u] = hreg;
                op[(size_t)(t0 + tl) * H_] = hreg;
            }
            p ^= 1;
            bar_sync(BAR);
        }
    }
}

extern "C" void kernel_launch(void* const* d_in, const int* in_sizes, int n_in,
                              void* d_out, int out_size)
{
    const float* noise = (const float*)d_in[0];
    const float* w_ih  = (const float*)d_in[1];
    const float* w_hh  = (const float*)d_in[2];
    const float* b_ih  = (const float*)d_in[3];
    const float* b_hh  = (const float*)d_in[4];
    float* out = (float*)d_out;

    const int SSZ = 3 * CHUNK * H_ + CHUNK * I_ + 2 * H_;
    const int smem = 2 * SSZ * (int)sizeof(float);
    cudaFuncSetAttribute(gru_kernel, cudaFuncAttributeMaxDynamicSharedMemorySize, smem);
    gru_kernel<<<B_ / 2, TPB, smem>>>(noise, w_ih, w_hh, b_ih, b_hh, out);
}

// round 6
// speedup vs baseline: 1.3133x; 1.3133x over previous
#include <cuda_runtime.h>

// GRU: B=256, T=2048, I=10, H=64. PyTorch gate order (r, z, n).
// grid=128 CTAs x 256 threads = 2 streams (1 batch each) x 128 threads.
// Lane pair (2u,2u+1) owns hidden unit u, computes all gates (r,z,n) over a
// 32-wide k-half; halves merge via shfl.bfly. One named barrier per step,
// double-buffered h. Changes this round: (a) stream-1 anti-phase skew so the
// two streams' fma phases interleave instead of colliding, (b) padded h
// layout (upper half +4 floats) to kill the even/odd-lane LDS bank conflict,
// (c) step loop unrolled x2 over buffer parity.

#define B_    256
#define T_    2048
#define I_    10
#define H_    64
#define CHUNK 32
#define TPB   256
#define STPB  128
#define HBS   68    // padded h buffer stride: [0,32) | 4 pad | [36,68)

typedef unsigned long long ull;

__device__ __forceinline__ ull ffma2(ull a, ull b, ull c) {
    ull d;
    asm("fma.rn.f32x2 %0, %1, %2, %3;" : "=l"(d) : "l"(a), "l"(b), "l"(c));
    return d;
}
__device__ __forceinline__ ull fadd2(ull a, ull b) {
    ull d;
    asm("add.rn.f32x2 %0, %1, %2;" : "=l"(d) : "l"(a), "l"(b));
    return d;
}
__device__ __forceinline__ ull pack2(float x, float y) {
    ull d;
    asm("mov.b64 %0, {%1, %2};" : "=l"(d) : "f"(x), "f"(y));
    return d;
}
__device__ __forceinline__ void unpack2(ull a, float& x, float& y) {
    asm("mov.b64 {%0, %1}, %2;" : "=f"(x), "=f"(y) : "l"(a));
}
__device__ __forceinline__ float tanha(float x) {
    float y;
    asm("tanh.approx.f32 %0, %1;" : "=f"(y) : "f"(x));
    return y;
}
__device__ __forceinline__ void bar_sync(int id) {
    asm volatile("bar.sync %0, %1;" :: "r"(id), "r"(STPB) : "memory");
}

__global__ void __launch_bounds__(TPB, 1)
gru_kernel(const float* __restrict__ noise,
           const float* __restrict__ w_ih,
           const float* __restrict__ w_hh,
           const float* __restrict__ b_ih,
           const float* __restrict__ b_hh,
           float* __restrict__ out)
{
    extern __shared__ __align__(16) char dync[];
    // per-stream: girz ull[CHUNK][H] | gin f32[CHUNK][H] | x f32[CHUNK*I] | h f32[2][HBS]
    const int GIRZ = CHUNK * H_;                 // ulls
    const int SSZf = CHUNK * H_ + CHUNK * I_ + 2 * HBS;   // floats after girz

    const int tid = threadIdx.x;
    const int s   = tid / STPB;
    const int ts  = tid % STPB;
    const int u   = ts >> 1;        // hidden unit
    const int e   = ts & 1;         // k-half: [32e, 32e+32)
    const int b   = blockIdx.x * 2 + s;
    const int k0  = 32 * e;
    const int BAR = 1 + s;

    ull*   girz = (ull*)dync + s * GIRZ;
    float* fbase = (float*)((ull*)dync + 2 * GIRZ);
    float* gin  = fbase + s * SSZf;
    float* xs   = gin + CHUNK * H_;
    float* hb   = xs + CHUNK * I_;

    // W_hh halves, packed by adjacent k-pairs.
    ull whr[16], whz[16], whn[16];
#pragma unroll
    for (int m = 0; m < 16; m++) {
        whr[m] = pack2(w_hh[(0 * H_ + u) * H_ + k0 + 2 * m], w_hh[(0 * H_ + u) * H_ + k0 + 2 * m + 1]);
        whz[m] = pack2(w_hh[(1 * H_ + u) * H_ + k0 + 2 * m], w_hh[(1 * H_ + u) * H_ + k0 + 2 * m + 1]);
        whn[m] = pack2(w_hh[(2 * H_ + u) * H_ + k0 + 2 * m], w_hh[(2 * H_ + u) * H_ + k0 + 2 * m + 1]);
    }
    ull wi[10];
    float bA = 0.0f, bB = 0.0f;
    if (e == 0) {
#pragma unroll
        for (int p = 0; p < 5; p++) {
            wi[p]     = pack2(w_ih[(0 * H_ + u) * I_ + 2 * p], w_ih[(0 * H_ + u) * I_ + 2 * p + 1]);
            wi[5 + p] = pack2(w_ih[(1 * H_ + u) * I_ + 2 * p], w_ih[(1 * H_ + u) * I_ + 2 * p + 1]);
        }
        bA = b_ih[0 * H_ + u] + b_hh[0 * H_ + u];
        bB = b_ih[1 * H_ + u] + b_hh[1 * H_ + u];
    } else {
#pragma unroll
        for (int p = 0; p < 5; p++)
            wi[p] = pack2(w_ih[(2 * H_ + u) * I_ + 2 * p], w_ih[(2 * H_ + u) * I_ + 2 * p + 1]);
        bA = b_ih[2 * H_ + u];
    }
    const float bhn = b_hh[2 * H_ + u];

    for (int idx = ts; idx < 2 * HBS; idx += STPB) hb[idx] = 0.0f;
    float hreg = 0.0f;
    const int hwidx = u + ((u >> 5) << 2);        // padded write index

    const float* xb = noise + (size_t)b * T_ * I_;
    float* op = out + (size_t)b * T_ * H_ + u;
    __syncthreads();

    // Anti-phase skew: stream 1 burns ~320 cycles once so the two streams'
    // compute phases interleave for the rest of the kernel.
    if (s == 1) {
        float acc = (float)tid;
#pragma unroll 1
        for (int i = 0; i < 80; i++)
            asm volatile("add.f32 %0, %0, 1.0;" : "+f"(acc));
        if (acc == -1.0f) hb[0] = acc;   // never true; keeps the chain live
    }

    // One timestep: read h buffer P, write buffer P^1.
#define STEP(P) do {                                                          \
        const ulonglong2* hq = (const ulonglong2*)(hb + (P) * HBS + 36 * e);  \
        ull r0 = 0ull, r1 = 0ull, z0 = 0ull, z1 = 0ull, n0 = 0ull, n1 = 0ull; \
        _Pragma("unroll")                                                     \
        for (int m = 0; m < 8; m++) {                                         \
            ulonglong2 h2 = hq[m];                                            \
            r0 = ffma2(h2.x, whr[2 * m], r0);                                 \
            z0 = ffma2(h2.x, whz[2 * m], z0);                                 \
            n0 = ffma2(h2.x, whn[2 * m], n0);                                 \
            r1 = ffma2(h2.y, whr[2 * m + 1], r1);                             \
            z1 = ffma2(h2.y, whz[2 * m + 1], z1);                             \
            n1 = ffma2(h2.y, whn[2 * m + 1], n1);                             \
        }                                                                     \
        float hvr, hvz, hvn;                                                  \
        {                                                                     \
            float x, y;                                                       \
            ull t2 = fadd2(r0, r1); unpack2(t2, x, y); hvr = x + y;           \
            t2 = fadd2(z0, z1);     unpack2(t2, x, y); hvz = x + y;           \
            t2 = fadd2(n0, n1);     unpack2(t2, x, y); hvn = x + y;           \
        }                                                                     \
        hvr += __shfl_xor_sync(0xffffffffu, hvr, 1);                          \
        hvz += __shfl_xor_sync(0xffffffffu, hvz, 1);                          \
        hvn += __shfl_xor_sync(0xffffffffu, hvn, 1);                          \
        float gr, gz;                                                         \
        unpack2(gp_rz[0], gr, gz);                                            \
        const float gn = gp_n[0];                                             \
        gp_rz += H_; gp_n += H_;                                              \
        const float r = fmaf(0.5f, tanha(0.5f * (gr + hvr)), 0.5f);           \
        const float z = fmaf(0.5f, tanha(0.5f * (gz + hvz)), 0.5f);           \
        const float n = tanha(fmaf(r, hvn + bhn, gn));                        \
        hreg = fmaf(z, hreg - n, n);                                          \
        if (e == 0) {                                                         \
            hb[((P) ^ 1) * HBS + hwidx] = hreg;                               \
            *op = hreg; op += H_;                                             \
        }                                                                     \
        bar_sync(BAR);                                                        \
    } while (0)

    for (int t0 = 0; t0 < T_; t0 += CHUNK) {
        for (int idx = ts; idx < CHUNK * I_; idx += STPB)
            xs[idx] = xb[t0 * I_ + idx];
        bar_sync(BAR);

        // gi precompute for the chunk.
        {
            const ull* xp = (const ull*)xs;
#pragma unroll 2
            for (int tl = 0; tl < CHUNK; tl++) {
                const ull* xt = xp + tl * (I_ / 2);
                if (e == 0) {
                    ull ar = 0ull, az = 0ull;
#pragma unroll
                    for (int q = 0; q < 5; q++) {
                        ull x2 = xt[q];
                        ar = ffma2(x2, wi[q], ar);
                        az = ffma2(x2, wi[5 + q], az);
                    }
                    float rx, ry, zx, zy;
                    unpack2(ar, rx, ry);
                    unpack2(az, zx, zy);
                    girz[tl * H_ + u] = pack2(rx + ry + bA, zx + zy + bB);
                } else {
                    ull an = 0ull;
#pragma unroll
                    for (int q = 0; q < 5; q++)
                        an = ffma2(xt[q], wi[q], an);
                    float nx, ny;
                    unpack2(an, nx, ny);
                    gin[tl * H_ + u] = nx + ny + bA;
                }
            }
        }
        bar_sync(BAR);

        const ull*   gp_rz = girz + u;
        const float* gp_n  = gin + u;
#pragma unroll 1
        for (int tl = 0; tl < CHUNK; tl += 2) {
            STEP(0);
            STEP(1);
        }
    }
#undef STEP
}

extern "C" void kernel_launch(void* const* d_in, const int* in_sizes, int n_in,
                              void* d_out, int out_size)
{
    const float* noise = (const float*)d_in[0];
    const float* w_ih  = (const float*)d_in[1];
    const float* w_hh  = (const float*)d_in[2];
    const float* b_ih  = (const float*)d_in[3];
    const float* b_hh  = (const float*)d_in[4];
    float* out = (float*)d_out;

    const int smem = 2 * (CHUNK * H_) * 8                       // girz
                   + 2 * (CHUNK * H_ + CHUNK * I_ + 2 * HBS) * 4; // gin + x + h
    cudaFuncSetAttribute(gru_kernel, cudaFuncAttributeMaxDynamicSharedMemorySize, smem);
    gru_kernel<<<B_ / 2, TPB, smem>>>(noise, w_ih, w_hh, b_ih, b_hh, out);
}

// round 7
// speedup vs baseline: 1.4548x; 1.1077x over previous
#include <cuda_runtime.h>

// GRU: B=256, T=2048, I=10, H=64. PyTorch gate order (r, z, n).
// grid=128 CTAs x 256 threads = 2 streams (1 batch each) x 128 threads.
// Lane pair (2u,2u+1) owns unit u, computes all gates over a 32-wide k-half;
// halves merge via shfl.bfly. One named barrier per step, double-buffered
// padded h. This round: x prefetched into registers across the step loop,
// gi stored as one 16B cell per (t,u) -> single broadcast LDS.128 per step,
// gi-phase work balanced across lane parity, stream-1 anti-phase skew kept.

#define B_    256
#define T_    2048
#define I_    10
#define H_    64
#define CHUNK 32
#define TPB   256
#define STPB  128
#define HBS   68    // padded h buffer stride: [0,32) | 4 pad | [36,68)
#define CELLS (CHUNK * H_)   // 16B gi cells per stream

typedef unsigned long long ull;

__device__ __forceinline__ ull ffma2(ull a, ull b, ull c) {
    ull d;
    asm("fma.rn.f32x2 %0, %1, %2, %3;" : "=l"(d) : "l"(a), "l"(b), "l"(c));
    return d;
}
__device__ __forceinline__ ull fadd2(ull a, ull b) {
    ull d;
    asm("add.rn.f32x2 %0, %1, %2;" : "=l"(d) : "l"(a), "l"(b));
    return d;
}
__device__ __forceinline__ ull pack2(float x, float y) {
    ull d;
    asm("mov.b64 %0, {%1, %2};" : "=l"(d) : "f"(x), "f"(y));
    return d;
}
__device__ __forceinline__ void unpack2(ull a, float& x, float& y) {
    asm("mov.b64 {%0, %1}, %2;" : "=f"(x), "=f"(y) : "l"(a));
}
__device__ __forceinline__ float tanha(float x) {
    float y;
    asm("tanh.approx.f32 %0, %1;" : "=f"(y) : "f"(x));
    return y;
}
__device__ __forceinline__ void bar_sync(int id) {
    asm volatile("bar.sync %0, %1;" :: "r"(id), "r"(STPB) : "memory");
}

__global__ void __launch_bounds__(TPB, 1)
gru_kernel(const float* __restrict__ noise,
           const float* __restrict__ w_ih,
           const float* __restrict__ w_hh,
           const float* __restrict__ b_ih,
           const float* __restrict__ b_hh,
           float* __restrict__ out)
{
    extern __shared__ __align__(16) char dync[];
    // layout: gcell ulonglong2[2][CELLS] | x f32[2][CHUNK*I] | h f32[2][2][HBS]

    const int tid = threadIdx.x;
    const int s   = tid / STPB;
    const int ts  = tid % STPB;
    const int u   = ts >> 1;        // hidden unit
    const int e   = ts & 1;         // k-half: [32e, 32e+32)
    const int b   = blockIdx.x * 2 + s;
    const int k0  = 32 * e;
    const int BAR = 1 + s;

    ulonglong2* gcell = (ulonglong2*)dync + s * CELLS;
    float* fbase = (float*)((ulonglong2*)dync + 2 * CELLS);
    float* xs = fbase + s * (CHUNK * I_);
    float* hb = fbase + 2 * (CHUNK * I_) + s * (2 * HBS);

    // W_hh halves, packed by adjacent k-pairs.
    ull whr[16], whz[16], whn[16];
#pragma unroll
    for (int m = 0; m < 16; m++) {
        whr[m] = pack2(w_hh[(0 * H_ + u) * H_ + k0 + 2 * m], w_hh[(0 * H_ + u) * H_ + k0 + 2 * m + 1]);
        whz[m] = pack2(w_hh[(1 * H_ + u) * H_ + k0 + 2 * m], w_hh[(1 * H_ + u) * H_ + k0 + 2 * m + 1]);
        whn[m] = pack2(w_hh[(2 * H_ + u) * H_ + k0 + 2 * m], w_hh[(2 * H_ + u) * H_ + k0 + 2 * m + 1]);
    }
    // All three W_ih rows on every lane (gi work alternates by t parity).
    ull wiR[5], wiZ[5], wiN[5];
#pragma unroll
    for (int p = 0; p < 5; p++) {
        wiR[p] = pack2(w_ih[(0 * H_ + u) * I_ + 2 * p], w_ih[(0 * H_ + u) * I_ + 2 * p + 1]);
        wiZ[p] = pack2(w_ih[(1 * H_ + u) * I_ + 2 * p], w_ih[(1 * H_ + u) * I_ + 2 * p + 1]);
        wiN[p] = pack2(w_ih[(2 * H_ + u) * I_ + 2 * p], w_ih[(2 * H_ + u) * I_ + 2 * p + 1]);
    }
    const float bA = b_ih[0 * H_ + u] + b_hh[0 * H_ + u];
    const float bB = b_ih[1 * H_ + u] + b_hh[1 * H_ + u];
    const float bC = b_ih[2 * H_ + u];
    const float bhn = b_hh[2 * H_ + u];

    for (int idx = ts; idx < 2 * HBS; idx += STPB) hb[idx] = 0.0f;
    float hreg = 0.0f;
    const int hwidx = u + ((u >> 5) << 2);        // padded write index

    const float* xb = noise + (size_t)b * T_ * I_;
    float* op = out + (size_t)b * T_ * H_ + u;

    // Prefetch chunk 0 x into registers.
    float xr0 = xb[ts];
    float xr1 = xb[ts + 128];
    float xr2 = (ts < CHUNK * I_ - 256) ? xb[ts + 256] : 0.0f;
    __syncthreads();

    // Anti-phase skew: stream 1 burns ~320 cycles once so the two streams'
    // compute phases interleave for the rest of the kernel.
    if (s == 1) {
        float acc = (float)tid;
#pragma unroll 1
        for (int i = 0; i < 80; i++)
            asm volatile("add.f32 %0, %0, 1.0;" : "+f"(acc));
        if (acc == -1.0f) hb[0] = acc;   // never true; keeps the chain live
    }

#define STEP(P) do {                                                          \
        const ulonglong2 gc = gp[0]; gp += H_;                                \
        const ulonglong2* hq = (const ulonglong2*)(hb + (P) * HBS + 36 * e);  \
        ull r0 = 0ull, r1 = 0ull, z0 = 0ull, z1 = 0ull, n0 = 0ull, n1 = 0ull; \
        _Pragma("unroll")                                                     \
        for (int m = 0; m < 8; m++) {                                         \
            ulonglong2 h2 = hq[m];                                            \
            r0 = ffma2(h2.x, whr[2 * m], r0);                                 \
            z0 = ffma2(h2.x, whz[2 * m], z0);                                 \
            n0 = ffma2(h2.x, whn[2 * m], n0);                                 \
            r1 = ffma2(h2.y, whr[2 * m + 1], r1);                             \
            z1 = ffma2(h2.y, whz[2 * m + 1], z1);                             \
            n1 = ffma2(h2.y, whn[2 * m + 1], n1);                             \
        }                                                                     \
        float hvr, hvz, hvn;                                                  \
        {                                                                     \
            float x, y;                                                       \
            ull t2 = fadd2(r0, r1); unpack2(t2, x, y); hvr = x + y;           \
            t2 = fadd2(z0, z1);     unpack2(t2, x, y); hvz = x + y;           \
            t2 = fadd2(n0, n1);     unpack2(t2, x, y); hvn = x + y;           \
        }                                                                     \
        hvr += __shfl_xor_sync(0xffffffffu, hvr, 1);                          \
        hvz += __shfl_xor_sync(0xffffffffu, hvz, 1);                          \
        hvn += __shfl_xor_sync(0xffffffffu, hvn, 1);                          \
        float gr, gz, gn, gpad;                                               \
        unpack2(gc.x, gr, gz);                                                \
        unpack2(gc.y, gn, gpad);                                              \
        const float r = fmaf(0.5f, tanha(0.5f * (gr + hvr)), 0.5f);           \
        const float z = fmaf(0.5f, tanha(0.5f * (gz + hvz)), 0.5f);           \
        const float n = tanha(fmaf(r, hvn + bhn, gn));                        \
        hreg = fmaf(z, hreg - n, n);                                          \
        if (e == 0) {                                                         \
            hb[((P) ^ 1) * HBS + hwidx] = hreg;                               \
            *op = hreg; op += H_;                                             \
        }                                                                     \
        bar_sync(BAR);                                                        \
    } while (0)

    for (int t0 = 0; t0 < T_; t0 += CHUNK) {
        // Commit prefetched x to shared.
        xs[ts] = xr0;
        xs[ts + 128] = xr1;
        if (ts < CHUNK * I_ - 256) xs[ts + 256] = xr2;
        bar_sync(BAR);

        // Prefetch next chunk's x (in flight across gi phase + step loop).
        {
            const float* xn = (t0 + CHUNK < T_) ? xb + (t0 + CHUNK) * I_ : xb;
            xr0 = xn[ts];
            xr1 = xn[ts + 128];
            if (ts < CHUNK * I_ - 256) xr2 = xn[ts + 256];
        }

        // gi precompute, balanced: role alternates with t parity.
        {
            const ull* xp = (const ull*)xs;
#pragma unroll 2
            for (int tl = 0; tl < CHUNK; tl++) {
                const ull* xt = xp + tl * (I_ / 2);
                ulonglong2* cell = gcell + tl * H_ + u;
                if (((tl ^ e) & 1) == 0) {
                    ull ar = 0ull, az = 0ull;
#pragma unroll
                    for (int q = 0; q < 5; q++) {
                        ull x2 = xt[q];
                        ar = ffma2(x2, wiR[q], ar);
                        az = ffma2(x2, wiZ[q], az);
                    }
                    float rx, ry, zx, zy;
                    unpack2(ar, rx, ry);
                    unpack2(az, zx, zy);
                    ((ull*)cell)[0] = pack2(rx + ry + bA, zx + zy + bB);
                } else {
                    ull an = 0ull;
#pragma unroll
                    for (int q = 0; q < 5; q++)
                        an = ffma2(xt[q], wiN[q], an);
                    float nx, ny;
                    unpack2(an, nx, ny);
                    ((float*)cell)[2] = nx + ny + bC;
                }
            }
        }
        bar_sync(BAR);

        const ulonglong2* gp = gcell + u;
#pragma unroll 1
        for (int tl = 0; tl < CHUNK; tl += 2) {
            STEP(0);
            STEP(1);
        }
    }
#undef STEP
}

extern "C" void kernel_launch(void* const* d_in, const int* in_sizes, int n_in,
                              void* d_out, int out_size)
{
    const float* noise = (const float*)d_in[0];
    const float* w_ih  = (const float*)d_in[1];
    const float* w_hh  = (const float*)d_in[2];
    const float* b_ih  = (const float*)d_in[3];
    const float* b_hh  = (const float*)d_in[4];
    float* out = (float*)d_out;

    const int smem = 2 * CELLS * 16            // gi cells
                   + 2 * CHUNK * I_ * 4        // x staging
                   + 2 * 2 * HBS * 4;          // h double buffers
    cudaFuncSetAttribute(gru_kernel, cudaFuncAttributeMaxDynamicSharedMemorySize, smem);
    gru_kernel<<<B_ / 2, TPB, smem>>>(noise, w_ih, w_hh, b_ih, b_hh, out);
}